// round 15
// baseline (speedup 1.0000x reference)
#include <cuda_runtime.h>

// Problem constants (shapes fixed by dataset)
#define MAXN 50000
#define MAXE 800000
#define NBLOCKS 444
#define PNT 128

// edge kernel: 256 threads, 256 edges/tile, 8 edges x 8 cols x 2 outputs per thread
#define ENT 256
#define EPB 256
#define EGRID 296      // 2 blocks/SM * 148 SMs

typedef unsigned long long u64;

// Scratch (allocation-free rule: __device__ globals).
__device__ __align__(256) float g_P[(size_t)MAXN * 128];   // [0:64)=emb@W1_top + b1, [64:128)=emb@W1_bot
__device__ __align__(256) float g_counts[MAXN];
__device__ __align__(256) float g_W2g[64 * 64];            // W2 @ Wg
__device__ __align__(256) float g_bgp[64];                 // b2 @ Wg + bg
__device__ int g_is64;

// ---------------- f32x2 helpers ----------------
__device__ __forceinline__ u64 pack2(float lo, float hi) {
    u64 r; asm("mov.b64 %0, {%1, %2};" : "=l"(r) : "f"(lo), "f"(hi)); return r;
}
__device__ __forceinline__ void unpack2(u64 v, float& lo, float& hi) {
    asm("mov.b64 {%0, %1}, %2;" : "=f"(lo), "=f"(hi) : "l"(v));
}
__device__ __forceinline__ u64 fma2(u64 a, u64 b, u64 c) {
    u64 d; asm("fma.rn.f32x2 %0, %1, %2, %3;" : "=l"(d) : "l"(a), "l"(b), "l"(c)); return d;
}
__device__ __forceinline__ void red4(float* p, float a, float b, float c, float d) {
    asm volatile("red.global.add.v4.f32 [%0], {%1, %2, %3, %4};"
                 :: "l"(p), "f"(a), "f"(b), "f"(c), "f"(d) : "memory");
}
__device__ __forceinline__ float sigmoidf_fast(float x) {
    return __fdividef(1.0f, 1.0f + __expf(-x));
}

// ---------------- dtype detect ----------------
__global__ void detect_kernel(const int* __restrict__ ei32) {
    int nz = 0;
    #pragma unroll
    for (int i = 1; i < 128; i += 2) nz |= ei32[i];
    g_is64 = (nz == 0) ? 1 : 0;
}

// ---------------- weight fusion: W2g = W2 @ Wg, bg' = b2 @ Wg + bg ----------------
__global__ void fuse_kernel(const float* __restrict__ W2, const float* __restrict__ b2,
                            const float* __restrict__ Wg, const float* __restrict__ bg) {
    __shared__ float Wgs[4096];
    __shared__ float b2s[64];
    int t = threadIdx.x;  // 256
    for (int i = t; i < 4096; i += 256) Wgs[i] = Wg[i];
    if (t < 64) b2s[t] = b2[t];
    __syncthreads();
    #pragma unroll 1
    for (int o = 0; o < 16; o++) {
        int idx = t * 16 + o;
        int k = idx >> 6, j = idx & 63;
        float s = 0.f;
        #pragma unroll 8
        for (int m = 0; m < 64; m++) s += W2[k * 64 + m] * Wgs[m * 64 + j];
        g_W2g[idx] = s;
    }
    if (t < 64) {
        float s = bg[t];
        #pragma unroll 8
        for (int m = 0; m < 64; m++) s += b2s[m] * Wgs[m * 64 + t];
        g_bgp[t] = s;
    }
}

// ---------------- zero init ----------------
__global__ void zero_kernel(float* __restrict__ out, int n_out4, int n_cnt4) {
    int i = blockIdx.x * blockDim.x + threadIdx.x;
    float4 z = make_float4(0.f, 0.f, 0.f, 0.f);
    if (i < n_out4) ((float4*)out)[i] = z;
    if (i < n_cnt4) ((float4*)g_counts)[i] = z;
}

// ---------------- proj matvec ----------------
__device__ __forceinline__ void matvec64(const float* Ws, const float* xcol, u64* acc) {
    #pragma unroll 4
    for (int k = 0; k < 64; k++) {
        float xk = xcol[k * PNT];
        u64 x2 = pack2(xk, xk);
        const ulonglong2* wr = (const ulonglong2*)(Ws + k * 64);
        #pragma unroll
        for (int q = 0; q < 16; q++) {
            ulonglong2 w = wr[q];
            acc[2 * q]     = fma2(x2, w.x, acc[2 * q]);
            acc[2 * q + 1] = fma2(x2, w.y, acc[2 * q + 1]);
        }
    }
}

// ---------------- node projection ----------------
__global__ void __launch_bounds__(PNT)
proj_kernel(const float* __restrict__ emb, const float* __restrict__ W1,
            const float* __restrict__ b1, int N) {
    extern __shared__ float sm[];
    float* W1s  = sm;           // 8192 floats
    float* xbuf = sm + 8192;    // 64*PNT
    __shared__ float b1s[64];

    int tid = threadIdx.x;
    for (int i = tid; i < 8192; i += PNT) W1s[i] = W1[i];
    if (tid < 64) b1s[tid] = b1[tid];
    __syncthreads();

    for (int base = blockIdx.x * PNT; base < N; base += gridDim.x * PNT) {
        int n = base + tid;
        if (n < N) {
            const float4* er = (const float4*)(emb + (size_t)n * 64);
            #pragma unroll
            for (int q = 0; q < 16; q++) {
                float4 v = er[q];
                xbuf[(4 * q + 0) * PNT + tid] = v.x;
                xbuf[(4 * q + 1) * PNT + tid] = v.y;
                xbuf[(4 * q + 2) * PNT + tid] = v.z;
                xbuf[(4 * q + 3) * PNT + tid] = v.w;
            }
            u64 acc[32];
            #pragma unroll
            for (int q = 0; q < 32; q++) acc[q] = pack2(b1s[2 * q], b1s[2 * q + 1]);
            matvec64(W1s, xbuf + tid, acc);
            float4* pr = (float4*)(g_P + (size_t)n * 128);
            #pragma unroll
            for (int t = 0; t < 16; t++) {
                float a, b, c, d;
                unpack2(acc[2 * t], a, b); unpack2(acc[2 * t + 1], c, d);
                pr[t] = make_float4(a, b, c, d);
            }
            #pragma unroll
            for (int q = 0; q < 32; q++) acc[q] = pack2(0.f, 0.f);
            matvec64(W1s + 64 * 64, xbuf + tid, acc);
            float4* pr2 = (float4*)(g_P + (size_t)n * 128 + 64);
            #pragma unroll
            for (int t = 0; t < 16; t++) {
                float a, b, c, d;
                unpack2(acc[2 * t], a, b); unpack2(acc[2 * t + 1], c, d);
                pr2[t] = make_float4(a, b, c, d);
            }
        }
    }
}

// ================= edge kernel v4: fused dual matvec =================
// smem (floats):
//   hs  : 16 chunks, stride 1028 (chunk kc: h[4kc..4kc+3][e] float4 at e*4, e<256)
//   W2p : 8 col-groups, stride 516; [c][k][8]
//   W2gp: same, from g_W2g
#define HS_STRIDE 1028
#define HS_FLOATS (16 * HS_STRIDE)        // 16448
#define WG_STRIDE 516
#define WP_FLOATS (8 * WG_STRIDE)         // 4128
#define EDGE_SMEM ((HS_FLOATS + 2 * WP_FLOATS) * 4)   // 98816 B

__global__ void __launch_bounds__(ENT)
edge_kernel(const void* __restrict__ ei_raw, const float* __restrict__ W2,
            const float* __restrict__ b2,
            float* __restrict__ out, int E, int N) {
    extern __shared__ float sm[];
    float* hs   = sm;
    float* W2p  = sm + HS_FLOATS;
    float* W2gp = sm + HS_FLOATS + WP_FLOATS;
    __shared__ int es[EPB];
    __shared__ int eds[EPB];
    __shared__ unsigned char ev[EPB];
    __shared__ __align__(16) float b2s[64], bgps[64];

    const int t = threadIdx.x;
    const int c = t & 7;        // col-group: cols 8c..8c+7
    const int p = t >> 3;       // 0..31; edge slots p + 32s, s=0..7

    // pack weights: W2p[c][k][8] = W2[k][8c+j]
    for (int idx = t; idx < 4096; idx += ENT) {
        int k = idx >> 6, col = idx & 63;
        int cc = col >> 3, j = col & 7;
        W2p [cc * WG_STRIDE + k * 8 + j] = W2[idx];
        W2gp[cc * WG_STRIDE + k * 8 + j] = g_W2g[idx];
    }
    if (t < 64) { b2s[t] = b2[t]; bgps[t] = g_bgp[t]; }

    const int is64 = g_is64;
    const int*       ei32 = (const int*)ei_raw;
    const long long* ei64 = (const long long*)ei_raw;

    const u64* bias2 = (const u64*)(b2s  + 8 * c);   // 4 u64
    const u64* biasg = (const u64*)(bgps + 8 * c);
    const float* Wc  = W2p  + c * WG_STRIDE;
    const float* Wgc = W2gp + c * WG_STRIDE;

    __syncthreads();

    for (int base = blockIdx.x * EPB; base < E; base += gridDim.x * EPB) {
        // ---- [A0] edge indices (coalesced), bounds-guarded ----
        {
            int e = base + t;
            int src = 0, dst = 0, valid = 0;
            if (e < E) {
                if (is64) { src = (int)ei64[e]; dst = (int)ei64[(size_t)E + e]; }
                else      { src = ei32[e];      dst = ei32[(size_t)E + e]; }
                valid = ((unsigned)src < (unsigned)N) && ((unsigned)dst < (unsigned)N);
                if (!valid) { src = 0; dst = 0; }
            }
            es[t] = src; eds[t] = dst; ev[t] = (unsigned char)valid;
        }
        __syncthreads();

        // ---- [A1] coalesced gather + relu -> hs ----
        #pragma unroll 4
        for (int j = 0; j < 16; j++) {
            int idx = j * ENT + t;           // 0..4095
            int e  = idx >> 4;               // 0..255
            int kc = idx & 15;
            int sN = es[e], dN = eds[e];
            float4 a = *(const float4*)(g_P + (size_t)sN * 128 + kc * 4);
            float4 b = *(const float4*)(g_P + (size_t)dN * 128 + 64 + kc * 4);
            float4 h;
            h.x = fmaxf(a.x + b.x, 0.f);
            h.y = fmaxf(a.y + b.y, 0.f);
            h.z = fmaxf(a.z + b.z, 0.f);
            h.w = fmaxf(a.w + b.w, 0.f);
            *(float4*)(hs + kc * HS_STRIDE + e * 4) = h;
        }
        __syncthreads();

        // ---- [B] fused: interaction = h@W2+b2, gate_pre = h@W2g+bg' ----
        u64 ai[32], ag[32];
        #pragma unroll
        for (int s = 0; s < 8; s++) {
            #pragma unroll
            for (int q = 0; q < 4; q++) {
                ai[s * 4 + q] = bias2[q];
                ag[s * 4 + q] = biasg[q];
            }
        }
        #pragma unroll 2
        for (int kc = 0; kc < 16; kc++) {
            const float* hrow = hs + kc * HS_STRIDE;
            float4 h[8];
            #pragma unroll
            for (int s = 0; s < 8; s++) h[s] = *(const float4*)(hrow + (p + 32 * s) * 4);
            #pragma unroll
            for (int i = 0; i < 4; i++) {
                const u64* w2r = (const u64*)(Wc  + (4 * kc + i) * 8);
                const u64* wgr = (const u64*)(Wgc + (4 * kc + i) * 8);
                u64 w20 = w2r[0], w21 = w2r[1], w22 = w2r[2], w23 = w2r[3];
                u64 wg0 = wgr[0], wg1 = wgr[1], wg2 = wgr[2], wg3 = wgr[3];
                #pragma unroll
                for (int s = 0; s < 8; s++) {
                    float hv = ((const float*)&h[s])[i];
                    u64 x = pack2(hv, hv);
                    ai[s * 4 + 0] = fma2(x, w20, ai[s * 4 + 0]);
                    ai[s * 4 + 1] = fma2(x, w21, ai[s * 4 + 1]);
                    ai[s * 4 + 2] = fma2(x, w22, ai[s * 4 + 2]);
                    ai[s * 4 + 3] = fma2(x, w23, ai[s * 4 + 3]);
                    ag[s * 4 + 0] = fma2(x, wg0, ag[s * 4 + 0]);
                    ag[s * 4 + 1] = fma2(x, wg1, ag[s * 4 + 1]);
                    ag[s * 4 + 2] = fma2(x, wg2, ag[s * 4 + 2]);
                    ag[s * 4 + 3] = fma2(x, wg3, ag[s * 4 + 3]);
                }
            }
        }

        // ---- [C] gated = interaction * sigmoid(gate_pre); scatter ----
        #pragma unroll
        for (int s = 0; s < 8; s++) {
            int slot = p + 32 * s;
            if (!ev[slot]) continue;
            int src = es[slot];
            float* orow = out + (size_t)src * 64 + c * 8;
            float r[8];
            #pragma unroll
            for (int q = 0; q < 4; q++) {
                float i0, i1, g0, g1;
                unpack2(ai[s * 4 + q], i0, i1);
                unpack2(ag[s * 4 + q], g0, g1);
                r[2 * q]     = i0 * sigmoidf_fast(g0);
                r[2 * q + 1] = i1 * sigmoidf_fast(g1);
            }
            red4(orow,     r[0], r[1], r[2], r[3]);
            red4(orow + 4, r[4], r[5], r[6], r[7]);
            if (c == 0) atomicAdd(&g_counts[src], 1.0f);
        }
        __syncthreads();   // protect hs/es before next tile
    }
}

// ---------------- normalize ----------------
__global__ void norm_kernel(float* __restrict__ out, int N) {
    int i = blockIdx.x * blockDim.x + threadIdx.x;
    if (i < N * 16) {
        int n = i >> 4;
        float cv = fmaxf(g_counts[n], 1.0f);
        float inv = 1.0f / cv;
        float4 v = ((float4*)out)[i];
        v.x *= inv; v.y *= inv; v.z *= inv; v.w *= inv;
        ((float4*)out)[i] = v;
    }
}

extern "C" void kernel_launch(void* const* d_in, const int* in_sizes, int n_in,
                              void* d_out, int out_size) {
    const float* emb = (const float*)d_in[0];
    const void*  ei  = d_in[1];
    const float* W1  = (const float*)d_in[2];
    const float* b1  = (const float*)d_in[3];
    const float* W2  = (const float*)d_in[4];
    const float* b2  = (const float*)d_in[5];
    const float* Wg  = (const float*)d_in[6];
    const float* bg  = (const float*)d_in[7];
    float* out = (float*)d_out;

    int N = in_sizes[0] / 64;
    int E = in_sizes[1] / 2;
    if (N > MAXN) N = MAXN;
    if (E > MAXE) E = MAXE;

    const int PROJ_SMEM = (8192 + 64 * PNT) * 4;   // 64KB
    cudaFuncSetAttribute(proj_kernel, cudaFuncAttributeMaxDynamicSharedMemorySize, PROJ_SMEM);
    cudaFuncSetAttribute(edge_kernel, cudaFuncAttributeMaxDynamicSharedMemorySize, EDGE_SMEM);

    int n_out4 = N * 16;
    int n_cnt4 = (N + 3) / 4;
    detect_kernel<<<1, 1>>>((const int*)ei);
    fuse_kernel<<<1, 256>>>(W2, b2, Wg, bg);
    zero_kernel<<<(n_out4 + 255) / 256, 256>>>(out, n_out4, n_cnt4);
    proj_kernel<<<NBLOCKS, PNT, PROJ_SMEM>>>(emb, W1, b1, N);
    edge_kernel<<<EGRID, ENT, EDGE_SMEM>>>(ei, W2, b2, out, E, N);
    norm_kernel<<<(N * 16 + 255) / 256, 256>>>(out, N);
}

// round 16
// speedup vs baseline: 1.0277x; 1.0277x over previous
#include <cuda_runtime.h>

// Problem constants (shapes fixed by dataset)
#define MAXN 50000
#define MAXE 800000
#define NBLOCKS 444
#define PNT 128

// edge kernel: 256 threads, 128 edges/tile, 4 edges x 8 cols x 2 outputs per thread
#define ENT 256
#define EPB 128
#define EGRID 296      // 2 blocks/SM * 148 SMs

typedef unsigned long long u64;

// Scratch (allocation-free rule: __device__ globals).
__device__ __align__(256) float g_P[(size_t)MAXN * 128];   // [0:64)=emb@W1_top + b1, [64:128)=emb@W1_bot
__device__ __align__(256) float g_counts[MAXN];
__device__ __align__(256) float g_W2g[64 * 64];            // W2 @ Wg
__device__ __align__(256) float g_bgp[64];                 // b2 @ Wg + bg
__device__ int g_is64;

// ---------------- f32x2 helpers ----------------
__device__ __forceinline__ u64 pack2(float lo, float hi) {
    u64 r; asm("mov.b64 %0, {%1, %2};" : "=l"(r) : "f"(lo), "f"(hi)); return r;
}
__device__ __forceinline__ void unpack2(u64 v, float& lo, float& hi) {
    asm("mov.b64 {%0, %1}, %2;" : "=f"(lo), "=f"(hi) : "l"(v));
}
__device__ __forceinline__ u64 fma2(u64 a, u64 b, u64 c) {
    u64 d; asm("fma.rn.f32x2 %0, %1, %2, %3;" : "=l"(d) : "l"(a), "l"(b), "l"(c)); return d;
}
__device__ __forceinline__ void red4(float* p, float a, float b, float c, float d) {
    asm volatile("red.global.add.v4.f32 [%0], {%1, %2, %3, %4};"
                 :: "l"(p), "f"(a), "f"(b), "f"(c), "f"(d) : "memory");
}
__device__ __forceinline__ float sigmoidf_fast(float x) {
    return __fdividef(1.0f, 1.0f + __expf(-x));
}

// ---------------- dtype detect ----------------
__global__ void detect_kernel(const int* __restrict__ ei32) {
    int nz = 0;
    #pragma unroll
    for (int i = 1; i < 128; i += 2) nz |= ei32[i];
    g_is64 = (nz == 0) ? 1 : 0;
}

// ---------------- weight fusion: W2g = W2 @ Wg, bg' = b2 @ Wg + bg ----------------
__global__ void fuse_kernel(const float* __restrict__ W2, const float* __restrict__ b2,
                            const float* __restrict__ Wg, const float* __restrict__ bg) {
    __shared__ float Wgs[4096];
    __shared__ float b2s[64];
    int t = threadIdx.x;  // 256
    for (int i = t; i < 4096; i += 256) Wgs[i] = Wg[i];
    if (t < 64) b2s[t] = b2[t];
    __syncthreads();
    #pragma unroll 1
    for (int o = 0; o < 16; o++) {
        int idx = t * 16 + o;
        int k = idx >> 6, j = idx & 63;
        float s = 0.f;
        #pragma unroll 8
        for (int m = 0; m < 64; m++) s += W2[k * 64 + m] * Wgs[m * 64 + j];
        g_W2g[idx] = s;
    }
    if (t < 64) {
        float s = bg[t];
        #pragma unroll 8
        for (int m = 0; m < 64; m++) s += b2s[m] * Wgs[m * 64 + t];
        g_bgp[t] = s;
    }
}

// ---------------- zero init ----------------
__global__ void zero_kernel(float* __restrict__ out, int n_out4, int n_cnt4) {
    int i = blockIdx.x * blockDim.x + threadIdx.x;
    float4 z = make_float4(0.f, 0.f, 0.f, 0.f);
    if (i < n_out4) ((float4*)out)[i] = z;
    if (i < n_cnt4) ((float4*)g_counts)[i] = z;
}

// ---------------- proj matvec ----------------
__device__ __forceinline__ void matvec64(const float* Ws, const float* xcol, u64* acc) {
    #pragma unroll 4
    for (int k = 0; k < 64; k++) {
        float xk = xcol[k * PNT];
        u64 x2 = pack2(xk, xk);
        const ulonglong2* wr = (const ulonglong2*)(Ws + k * 64);
        #pragma unroll
        for (int q = 0; q < 16; q++) {
            ulonglong2 w = wr[q];
            acc[2 * q]     = fma2(x2, w.x, acc[2 * q]);
            acc[2 * q + 1] = fma2(x2, w.y, acc[2 * q + 1]);
        }
    }
}

// ---------------- node projection ----------------
__global__ void __launch_bounds__(PNT)
proj_kernel(const float* __restrict__ emb, const float* __restrict__ W1,
            const float* __restrict__ b1, int N) {
    extern __shared__ float sm[];
    float* W1s  = sm;           // 8192 floats
    float* xbuf = sm + 8192;    // 64*PNT
    __shared__ float b1s[64];

    int tid = threadIdx.x;
    for (int i = tid; i < 8192; i += PNT) W1s[i] = W1[i];
    if (tid < 64) b1s[tid] = b1[tid];
    __syncthreads();

    for (int base = blockIdx.x * PNT; base < N; base += gridDim.x * PNT) {
        int n = base + tid;
        if (n < N) {
            const float4* er = (const float4*)(emb + (size_t)n * 64);
            #pragma unroll
            for (int q = 0; q < 16; q++) {
                float4 v = er[q];
                xbuf[(4 * q + 0) * PNT + tid] = v.x;
                xbuf[(4 * q + 1) * PNT + tid] = v.y;
                xbuf[(4 * q + 2) * PNT + tid] = v.z;
                xbuf[(4 * q + 3) * PNT + tid] = v.w;
            }
            u64 acc[32];
            #pragma unroll
            for (int q = 0; q < 32; q++) acc[q] = pack2(b1s[2 * q], b1s[2 * q + 1]);
            matvec64(W1s, xbuf + tid, acc);
            float4* pr = (float4*)(g_P + (size_t)n * 128);
            #pragma unroll
            for (int t = 0; t < 16; t++) {
                float a, b, c, d;
                unpack2(acc[2 * t], a, b); unpack2(acc[2 * t + 1], c, d);
                pr[t] = make_float4(a, b, c, d);
            }
            #pragma unroll
            for (int q = 0; q < 32; q++) acc[q] = pack2(0.f, 0.f);
            matvec64(W1s + 64 * 64, xbuf + tid, acc);
            float4* pr2 = (float4*)(g_P + (size_t)n * 128 + 64);
            #pragma unroll
            for (int t = 0; t < 16; t++) {
                float a, b, c, d;
                unpack2(acc[2 * t], a, b); unpack2(acc[2 * t + 1], c, d);
                pr2[t] = make_float4(a, b, c, d);
            }
        }
    }
}

// ================= edge kernel v5: fused dual matvec, no-spill tiling =================
// 256 threads, 128 edges/tile. Thread (c = t&7, p = t>>3): cols 8c..8c+7, edges p+32s (s=0..3).
// smem (floats):
//   hs  : 16 chunks, stride 516 (chunk kc: h[4kc..4kc+3][e] float4 at e*4, e<128)
//   W2p : 8 col-groups, stride 516; [c][k][8]
//   W2gp: same, from g_W2g
#define HS_STRIDE 516
#define HS_FLOATS (16 * HS_STRIDE)        // 8256
#define WG_STRIDE 516
#define WP_FLOATS (8 * WG_STRIDE)         // 4128
#define EDGE_SMEM ((HS_FLOATS + 2 * WP_FLOATS) * 4)   // 66048 B

__global__ void __launch_bounds__(ENT, 2)
edge_kernel(const void* __restrict__ ei_raw, const float* __restrict__ W2,
            const float* __restrict__ b2,
            float* __restrict__ out, int E, int N) {
    extern __shared__ float sm[];
    float* hs   = sm;
    float* W2p  = sm + HS_FLOATS;
    float* W2gp = sm + HS_FLOATS + WP_FLOATS;
    __shared__ int es[EPB];
    __shared__ int eds[EPB];
    __shared__ unsigned char ev[EPB];
    __shared__ __align__(16) float b2s[64], bgps[64];

    const int t = threadIdx.x;
    const int c = t & 7;        // col-group: cols 8c..8c+7
    const int p = t >> 3;       // 0..31; edge slots p + 32s, s=0..3

    // pack weights: W2p[c][k][8] = W2[k][8c+j]
    for (int idx = t; idx < 4096; idx += ENT) {
        int k = idx >> 6, col = idx & 63;
        int cc = col >> 3, j = col & 7;
        W2p [cc * WG_STRIDE + k * 8 + j] = W2[idx];
        W2gp[cc * WG_STRIDE + k * 8 + j] = g_W2g[idx];
    }
    if (t < 64) { b2s[t] = b2[t]; bgps[t] = g_bgp[t]; }

    const int is64 = g_is64;
    const int*       ei32 = (const int*)ei_raw;
    const long long* ei64 = (const long long*)ei_raw;

    const u64* bias2 = (const u64*)(b2s  + 8 * c);   // 4 u64
    const u64* biasg = (const u64*)(bgps + 8 * c);
    const float* Wc  = W2p  + c * WG_STRIDE;
    const float* Wgc = W2gp + c * WG_STRIDE;

    __syncthreads();

    for (int base = blockIdx.x * EPB; base < E; base += gridDim.x * EPB) {
        // ---- [A0] edge indices (first 128 threads, coalesced), bounds-guarded ----
        if (t < EPB) {
            int e = base + t;
            int src = 0, dst = 0, valid = 0;
            if (e < E) {
                if (is64) { src = (int)ei64[e]; dst = (int)ei64[(size_t)E + e]; }
                else      { src = ei32[e];      dst = ei32[(size_t)E + e]; }
                valid = ((unsigned)src < (unsigned)N) && ((unsigned)dst < (unsigned)N);
                if (!valid) { src = 0; dst = 0; }
            }
            es[t] = src; eds[t] = dst; ev[t] = (unsigned char)valid;
        }
        __syncthreads();

        // ---- [A1] coalesced gather + relu -> hs (2048 float4 slots / 256 thr = 8 iters) ----
        #pragma unroll 4
        for (int j = 0; j < 8; j++) {
            int idx = j * ENT + t;           // 0..2047
            int e  = idx >> 4;               // 0..127
            int kc = idx & 15;
            int sN = es[e], dN = eds[e];
            float4 a = *(const float4*)(g_P + (size_t)sN * 128 + kc * 4);
            float4 b = *(const float4*)(g_P + (size_t)dN * 128 + 64 + kc * 4);
            float4 h;
            h.x = fmaxf(a.x + b.x, 0.f);
            h.y = fmaxf(a.y + b.y, 0.f);
            h.z = fmaxf(a.z + b.z, 0.f);
            h.w = fmaxf(a.w + b.w, 0.f);
            *(float4*)(hs + kc * HS_STRIDE + e * 4) = h;
        }
        __syncthreads();

        // ---- [B] fused: interaction = h@W2+b2 ; gate_pre = h@W2g+bg' ----
        u64 ai[16], ag[16];
        #pragma unroll
        for (int s = 0; s < 4; s++) {
            #pragma unroll
            for (int q = 0; q < 4; q++) {
                ai[s * 4 + q] = bias2[q];
                ag[s * 4 + q] = biasg[q];
            }
        }
        #pragma unroll 1
        for (int kc = 0; kc < 16; kc++) {
            const float* hrow = hs + kc * HS_STRIDE;
            float4 h0 = *(const float4*)(hrow + (p +  0) * 4);
            float4 h1 = *(const float4*)(hrow + (p + 32) * 4);
            float4 h2 = *(const float4*)(hrow + (p + 64) * 4);
            float4 h3 = *(const float4*)(hrow + (p + 96) * 4);
            const float* f0 = (const float*)&h0;
            const float* f1 = (const float*)&h1;
            const float* f2 = (const float*)&h2;
            const float* f3 = (const float*)&h3;
            #pragma unroll
            for (int i = 0; i < 4; i++) {
                const ulonglong2* w2r = (const ulonglong2*)(Wc  + (4 * kc + i) * 8);
                const ulonglong2* wgr = (const ulonglong2*)(Wgc + (4 * kc + i) * 8);
                ulonglong2 wa = w2r[0], wb = w2r[1];     // 2x LDS.128 (broadcast)
                ulonglong2 ga = wgr[0], gb = wgr[1];
                u64 x0 = pack2(f0[i], f0[i]);
                u64 x1 = pack2(f1[i], f1[i]);
                u64 x2 = pack2(f2[i], f2[i]);
                u64 x3 = pack2(f3[i], f3[i]);
                ai[0]  = fma2(x0, wa.x, ai[0]);  ai[1]  = fma2(x0, wa.y, ai[1]);
                ai[2]  = fma2(x0, wb.x, ai[2]);  ai[3]  = fma2(x0, wb.y, ai[3]);
                ag[0]  = fma2(x0, ga.x, ag[0]);  ag[1]  = fma2(x0, ga.y, ag[1]);
                ag[2]  = fma2(x0, gb.x, ag[2]);  ag[3]  = fma2(x0, gb.y, ag[3]);
                ai[4]  = fma2(x1, wa.x, ai[4]);  ai[5]  = fma2(x1, wa.y, ai[5]);
                ai[6]  = fma2(x1, wb.x, ai[6]);  ai[7]  = fma2(x1, wb.y, ai[7]);
                ag[4]  = fma2(x1, ga.x, ag[4]);  ag[5]  = fma2(x1, ga.y, ag[5]);
                ag[6]  = fma2(x1, gb.x, ag[6]);  ag[7]  = fma2(x1, gb.y, ag[7]);
                ai[8]  = fma2(x2, wa.x, ai[8]);  ai[9]  = fma2(x2, wa.y, ai[9]);
                ai[10] = fma2(x2, wb.x, ai[10]); ai[11] = fma2(x2, wb.y, ai[11]);
                ag[8]  = fma2(x2, ga.x, ag[8]);  ag[9]  = fma2(x2, ga.y, ag[9]);
                ag[10] = fma2(x2, gb.x, ag[10]); ag[11] = fma2(x2, gb.y, ag[11]);
                ai[12] = fma2(x3, wa.x, ai[12]); ai[13] = fma2(x3, wa.y, ai[13]);
                ai[14] = fma2(x3, wb.x, ai[14]); ai[15] = fma2(x3, wb.y, ai[15]);
                ag[12] = fma2(x3, ga.x, ag[12]); ag[13] = fma2(x3, ga.y, ag[13]);
                ag[14] = fma2(x3, gb.x, ag[14]); ag[15] = fma2(x3, gb.y, ag[15]);
            }
        }

        // ---- [C] gated = interaction * sigmoid(gate_pre); scatter ----
        #pragma unroll
        for (int s = 0; s < 4; s++) {
            int slot = p + 32 * s;
            if (!ev[slot]) continue;
            int src = es[slot];
            float* orow = out + (size_t)src * 64 + c * 8;
            float r[8];
            #pragma unroll
            for (int q = 0; q < 4; q++) {
                float i0, i1, g0, g1;
                unpack2(ai[s * 4 + q], i0, i1);
                unpack2(ag[s * 4 + q], g0, g1);
                r[2 * q]     = i0 * sigmoidf_fast(g0);
                r[2 * q + 1] = i1 * sigmoidf_fast(g1);
            }
            red4(orow,     r[0], r[1], r[2], r[3]);
            red4(orow + 4, r[4], r[5], r[6], r[7]);
            if (c == 0) atomicAdd(&g_counts[src], 1.0f);
        }
        __syncthreads();   // protect hs/es before next tile
    }
}

// ---------------- normalize ----------------
__global__ void norm_kernel(float* __restrict__ out, int N) {
    int i = blockIdx.x * blockDim.x + threadIdx.x;
    if (i < N * 16) {
        int n = i >> 4;
        float cv = fmaxf(g_counts[n], 1.0f);
        float inv = 1.0f / cv;
        float4 v = ((float4*)out)[i];
        v.x *= inv; v.y *= inv; v.z *= inv; v.w *= inv;
        ((float4*)out)[i] = v;
    }
}

extern "C" void kernel_launch(void* const* d_in, const int* in_sizes, int n_in,
                              void* d_out, int out_size) {
    const float* emb = (const float*)d_in[0];
    const void*  ei  = d_in[1];
    const float* W1  = (const float*)d_in[2];
    const float* b1  = (const float*)d_in[3];
    const float* W2  = (const float*)d_in[4];
    const float* b2  = (const float*)d_in[5];
    const float* Wg  = (const float*)d_in[6];
    const float* bg  = (const float*)d_in[7];
    float* out = (float*)d_out;

    int N = in_sizes[0] / 64;
    int E = in_sizes[1] / 2;
    if (N > MAXN) N = MAXN;
    if (E > MAXE) E = MAXE;

    const int PROJ_SMEM = (8192 + 64 * PNT) * 4;   // 64KB
    cudaFuncSetAttribute(proj_kernel, cudaFuncAttributeMaxDynamicSharedMemorySize, PROJ_SMEM);
    cudaFuncSetAttribute(edge_kernel, cudaFuncAttributeMaxDynamicSharedMemorySize, EDGE_SMEM);

    int n_out4 = N * 16;
    int n_cnt4 = (N + 3) / 4;
    detect_kernel<<<1, 1>>>((const int*)ei);
    fuse_kernel<<<1, 256>>>(W2, b2, Wg, bg);
    zero_kernel<<<(n_out4 + 255) / 256, 256>>>(out, n_out4, n_cnt4);
    proj_kernel<<<NBLOCKS, PNT, PROJ_SMEM>>>(emb, W1, b1, N);
    edge_kernel<<<EGRID, ENT, EDGE_SMEM>>>(ei, W2, b2, out, E, N);
    norm_kernel<<<(N * 16 + 255) / 256, 256>>>(out, N);
}

// round 17
// speedup vs baseline: 1.1727x; 1.1411x over previous
#include <cuda_runtime.h>

// Problem constants (shapes fixed by dataset)
#define MAXN 50000
#define MAXE 800000
#define NBLOCKS 444
#define PNT 128

// edge kernel: 256 threads, 256 edges/tile, 8 edges x 8 cols per thread, two passes
#define ENT 256
#define EPB 256
#define EGRID 296      // 2 blocks/SM * 148 SMs

typedef unsigned long long u64;

// Scratch (allocation-free rule: __device__ globals).
__device__ __align__(256) float g_P[(size_t)MAXN * 128];   // [0:64)=emb@W1_top + b1, [64:128)=emb@W1_bot
__device__ __align__(256) float g_counts[MAXN];
__device__ int g_is64;

// ---------------- f32x2 helpers ----------------
__device__ __forceinline__ u64 pack2(float lo, float hi) {
    u64 r; asm("mov.b64 %0, {%1, %2};" : "=l"(r) : "f"(lo), "f"(hi)); return r;
}
__device__ __forceinline__ void unpack2(u64 v, float& lo, float& hi) {
    asm("mov.b64 {%0, %1}, %2;" : "=f"(lo), "=f"(hi) : "l"(v));
}
__device__ __forceinline__ u64 fma2(u64 a, u64 b, u64 c) {
    u64 d; asm("fma.rn.f32x2 %0, %1, %2, %3;" : "=l"(d) : "l"(a), "l"(b), "l"(c)); return d;
}
__device__ __forceinline__ void red4(float* p, float a, float b, float c, float d) {
    asm volatile("red.global.add.v4.f32 [%0], {%1, %2, %3, %4};"
                 :: "l"(p), "f"(a), "f"(b), "f"(c), "f"(d) : "memory");
}
__device__ __forceinline__ float sigmoidf_fast(float x) {
    return __fdividef(1.0f, 1.0f + __expf(-x));
}

// ---------------- dtype detect ----------------
__global__ void detect_kernel(const int* __restrict__ ei32) {
    int nz = 0;
    #pragma unroll
    for (int i = 1; i < 128; i += 2) nz |= ei32[i];
    g_is64 = (nz == 0) ? 1 : 0;
}

// ---------------- zero init ----------------
__global__ void zero_kernel(float* __restrict__ out, int n_out4, int n_cnt4) {
    int i = blockIdx.x * blockDim.x + threadIdx.x;
    float4 z = make_float4(0.f, 0.f, 0.f, 0.f);
    if (i < n_out4) ((float4*)out)[i] = z;
    if (i < n_cnt4) ((float4*)g_counts)[i] = z;
}

// ---------------- proj matvec ----------------
__device__ __forceinline__ void matvec64(const float* Ws, const float* xcol, u64* acc) {
    #pragma unroll 4
    for (int k = 0; k < 64; k++) {
        float xk = xcol[k * PNT];
        u64 x2 = pack2(xk, xk);
        const ulonglong2* wr = (const ulonglong2*)(Ws + k * 64);
        #pragma unroll
        for (int q = 0; q < 16; q++) {
            ulonglong2 w = wr[q];
            acc[2 * q]     = fma2(x2, w.x, acc[2 * q]);
            acc[2 * q + 1] = fma2(x2, w.y, acc[2 * q + 1]);
        }
    }
}

// ---------------- node projection ----------------
__global__ void __launch_bounds__(PNT)
proj_kernel(const float* __restrict__ emb, const float* __restrict__ W1,
            const float* __restrict__ b1, int N) {
    extern __shared__ float sm[];
    float* W1s  = sm;           // 8192 floats
    float* xbuf = sm + 8192;    // 64*PNT
    __shared__ float b1s[64];

    int tid = threadIdx.x;
    for (int i = tid; i < 8192; i += PNT) W1s[i] = W1[i];
    if (tid < 64) b1s[tid] = b1[tid];
    __syncthreads();

    for (int base = blockIdx.x * PNT; base < N; base += gridDim.x * PNT) {
        int n = base + tid;
        if (n < N) {
            const float4* er = (const float4*)(emb + (size_t)n * 64);
            #pragma unroll
            for (int q = 0; q < 16; q++) {
                float4 v = er[q];
                xbuf[(4 * q + 0) * PNT + tid] = v.x;
                xbuf[(4 * q + 1) * PNT + tid] = v.y;
                xbuf[(4 * q + 2) * PNT + tid] = v.z;
                xbuf[(4 * q + 3) * PNT + tid] = v.w;
            }
            u64 acc[32];
            #pragma unroll
            for (int q = 0; q < 32; q++) acc[q] = pack2(b1s[2 * q], b1s[2 * q + 1]);
            matvec64(W1s, xbuf + tid, acc);
            float4* pr = (float4*)(g_P + (size_t)n * 128);
            #pragma unroll
            for (int t = 0; t < 16; t++) {
                float a, b, c, d;
                unpack2(acc[2 * t], a, b); unpack2(acc[2 * t + 1], c, d);
                pr[t] = make_float4(a, b, c, d);
            }
            #pragma unroll
            for (int q = 0; q < 32; q++) acc[q] = pack2(0.f, 0.f);
            matvec64(W1s + 64 * 64, xbuf + tid, acc);
            float4* pr2 = (float4*)(g_P + (size_t)n * 128 + 64);
            #pragma unroll
            for (int t = 0; t < 16; t++) {
                float a, b, c, d;
                unpack2(acc[2 * t], a, b); unpack2(acc[2 * t + 1], c, d);
                pr2[t] = make_float4(a, b, c, d);
            }
        }
    }
}

// ================= edge kernel v6: two-pass, balanced 8 edges x 8 cols =================
// 256 threads, 256 edges/tile. Thread (c = t&7, p = t>>3): cols 8c..8c+7, edges p+32s (s=0..7).
// smem (floats):
//   hs  : 16 chunks, stride 1028 (chunk kc: vec[4kc..4kc+3][e] float4 at e*4, e<256)
//   W2p : 8 col-groups, stride 516; [c][k][8]
//   Wgp : same
#define HS_STRIDE 1028
#define HS_FLOATS (16 * HS_STRIDE)        // 16448
#define WG_STRIDE 516
#define WP_FLOATS (8 * WG_STRIDE)         // 4128
#define EDGE_SMEM ((HS_FLOATS + 2 * WP_FLOATS) * 4)   // 98816 B

// mv8x8: this thread's 8 cols (weights at Wc) for its 8 edges (slots p+32s in hs).
// acc[s*4+q], s=0..7 edges, q=0..3 (4 u64 = 8 cols).
__device__ __forceinline__ void mv8x8(const float* __restrict__ Wc,
                                      const float* __restrict__ hsb,
                                      int p, const u64* __restrict__ biasc,
                                      u64 acc[32]) {
    #pragma unroll
    for (int s = 0; s < 8; s++) {
        #pragma unroll
        for (int q = 0; q < 4; q++) acc[s * 4 + q] = biasc[q];
    }
    #pragma unroll 2
    for (int kc = 0; kc < 16; kc++) {
        const float* hrow = hsb + kc * HS_STRIDE;
        float4 h[8];
        #pragma unroll
        for (int s = 0; s < 8; s++) h[s] = *(const float4*)(hrow + (p + 32 * s) * 4);
        #pragma unroll
        for (int i = 0; i < 4; i++) {
            const ulonglong2* wr = (const ulonglong2*)(Wc + (4 * kc + i) * 8);
            ulonglong2 wa = wr[0], wb = wr[1];   // 2x LDS.128 broadcast
            #pragma unroll
            for (int s = 0; s < 8; s++) {
                float hv = ((const float*)&h[s])[i];
                u64 x = pack2(hv, hv);
                acc[s * 4 + 0] = fma2(x, wa.x, acc[s * 4 + 0]);
                acc[s * 4 + 1] = fma2(x, wa.y, acc[s * 4 + 1]);
                acc[s * 4 + 2] = fma2(x, wb.x, acc[s * 4 + 2]);
                acc[s * 4 + 3] = fma2(x, wb.y, acc[s * 4 + 3]);
            }
        }
    }
}

__global__ void __launch_bounds__(ENT, 2)
edge_kernel(const void* __restrict__ ei_raw, const float* __restrict__ W2,
            const float* __restrict__ b2, const float* __restrict__ Wg,
            const float* __restrict__ bg,
            float* __restrict__ out, int E, int N) {
    extern __shared__ float sm[];
    float* hs  = sm;
    float* W2p = sm + HS_FLOATS;
    float* Wgp = sm + HS_FLOATS + WP_FLOATS;
    __shared__ int es[EPB];
    __shared__ int eds[EPB];
    __shared__ unsigned char ev[EPB];
    __shared__ __align__(16) float b2s[64], bgs[64];

    const int t = threadIdx.x;
    const int c = t & 7;        // col-group: cols 8c..8c+7
    const int p = t >> 3;       // 0..31; edge slots p + 32s, s=0..7

    // pack weights: W2p[c][k][8] = W2[k][8c+j]
    for (int idx = t; idx < 4096; idx += ENT) {
        int k = idx >> 6, col = idx & 63;
        int cc = col >> 3, j = col & 7;
        W2p[cc * WG_STRIDE + k * 8 + j] = W2[idx];
        Wgp[cc * WG_STRIDE + k * 8 + j] = Wg[idx];
    }
    if (t < 64) { b2s[t] = b2[t]; bgs[t] = bg[t]; }

    const int is64 = g_is64;
    const int*       ei32 = (const int*)ei_raw;
    const long long* ei64 = (const long long*)ei_raw;

    const u64* bias2 = (const u64*)(b2s + 8 * c);   // 4 u64
    const u64* biasg = (const u64*)(bgs + 8 * c);
    const float* Wc  = W2p + c * WG_STRIDE;
    const float* Wgc = Wgp + c * WG_STRIDE;

    __syncthreads();

    for (int base = blockIdx.x * EPB; base < E; base += gridDim.x * EPB) {
        // ---- [A0] edge indices (coalesced), bounds-guarded ----
        {
            int e = base + t;
            int src = 0, dst = 0, valid = 0;
            if (e < E) {
                if (is64) { src = (int)ei64[e]; dst = (int)ei64[(size_t)E + e]; }
                else      { src = ei32[e];      dst = ei32[(size_t)E + e]; }
                valid = ((unsigned)src < (unsigned)N) && ((unsigned)dst < (unsigned)N);
                if (!valid) { src = 0; dst = 0; }
            }
            es[t] = src; eds[t] = dst; ev[t] = (unsigned char)valid;
        }
        __syncthreads();

        // ---- [A1] coalesced gather + relu -> hs ----
        #pragma unroll 4
        for (int j = 0; j < 16; j++) {
            int idx = j * ENT + t;           // 0..4095
            int e  = idx >> 4;               // 0..255
            int kc = idx & 15;
            int sN = es[e], dN = eds[e];
            float4 a = *(const float4*)(g_P + (size_t)sN * 128 + kc * 4);
            float4 b = *(const float4*)(g_P + (size_t)dN * 128 + 64 + kc * 4);
            float4 h;
            h.x = fmaxf(a.x + b.x, 0.f);
            h.y = fmaxf(a.y + b.y, 0.f);
            h.z = fmaxf(a.z + b.z, 0.f);
            h.w = fmaxf(a.w + b.w, 0.f);
            *(float4*)(hs + kc * HS_STRIDE + e * 4) = h;
        }
        __syncthreads();

        // ---- [B] pass 1: interaction = h @ W2 + b2 ----
        u64 acc[32];
        mv8x8(Wc, hs, p, bias2, acc);
        __syncthreads();   // all h reads done before stash overwrites

        // ---- [C] stash interaction into hs (chunks 2c, 2c+1) ----
        #pragma unroll
        for (int s = 0; s < 8; s++) {
            int e = p + 32 * s;
            #pragma unroll
            for (int m = 0; m < 2; m++) {
                float a, b;
                float cc, d;
                unpack2(acc[s * 4 + 2 * m], a, b);
                unpack2(acc[s * 4 + 2 * m + 1], cc, d);
                *(float4*)(hs + (2 * c + m) * HS_STRIDE + e * 4) = make_float4(a, b, cc, d);
            }
        }
        __syncthreads();

        // ---- [D] pass 2: gate_pre = interaction @ Wg + bg; sigmoid; scatter ----
        mv8x8(Wgc, hs, p, biasg, acc);

        #pragma unroll
        for (int s = 0; s < 8; s++) {
            int slot = p + 32 * s;
            if (!ev[slot]) continue;
            int src = es[slot];
            float* orow = out + (size_t)src * 64 + c * 8;
            float r[8];
            #pragma unroll
            for (int m = 0; m < 2; m++) {
                float g0, g1, g2, g3;
                unpack2(acc[s * 4 + 2 * m], g0, g1);
                unpack2(acc[s * 4 + 2 * m + 1], g2, g3);
                float4 inter = *(const float4*)(hs + (2 * c + m) * HS_STRIDE + slot * 4);
                r[4 * m + 0] = inter.x * sigmoidf_fast(g0);
                r[4 * m + 1] = inter.y * sigmoidf_fast(g1);
                r[4 * m + 2] = inter.z * sigmoidf_fast(g2);
                r[4 * m + 3] = inter.w * sigmoidf_fast(g3);
            }
            red4(orow,     r[0], r[1], r[2], r[3]);
            red4(orow + 4, r[4], r[5], r[6], r[7]);
            if (c == 0) atomicAdd(&g_counts[src], 1.0f);
        }
        __syncthreads();   // protect hs/es before next tile
    }
}

// ---------------- normalize ----------------
__global__ void norm_kernel(float* __restrict__ out, int N) {
    int i = blockIdx.x * blockDim.x + threadIdx.x;
    if (i < N * 16) {
        int n = i >> 4;
        float cv = fmaxf(g_counts[n], 1.0f);
        float inv = 1.0f / cv;
        float4 v = ((float4*)out)[i];
        v.x *= inv; v.y *= inv; v.z *= inv; v.w *= inv;
        ((float4*)out)[i] = v;
    }
}

extern "C" void kernel_launch(void* const* d_in, const int* in_sizes, int n_in,
                              void* d_out, int out_size) {
    const float* emb = (const float*)d_in[0];
    const void*  ei  = d_in[1];
    const float* W1  = (const float*)d_in[2];
    const float* b1  = (const float*)d_in[3];
    const float* W2  = (const float*)d_in[4];
    const float* b2  = (const float*)d_in[5];
    const float* Wg  = (const float*)d_in[6];
    const float* bg  = (const float*)d_in[7];
    float* out = (float*)d_out;

    int N = in_sizes[0] / 64;
    int E = in_sizes[1] / 2;
    if (N > MAXN) N = MAXN;
    if (E > MAXE) E = MAXE;

    const int PROJ_SMEM = (8192 + 64 * PNT) * 4;   // 64KB
    cudaFuncSetAttribute(proj_kernel, cudaFuncAttributeMaxDynamicSharedMemorySize, PROJ_SMEM);
    cudaFuncSetAttribute(edge_kernel, cudaFuncAttributeMaxDynamicSharedMemorySize, EDGE_SMEM);

    int n_out4 = N * 16;
    int n_cnt4 = (N + 3) / 4;
    detect_kernel<<<1, 1>>>((const int*)ei);
    zero_kernel<<<(n_out4 + 255) / 256, 256>>>(out, n_out4, n_cnt4);
    proj_kernel<<<NBLOCKS, PNT, PROJ_SMEM>>>(emb, W1, b1, N);
    edge_kernel<<<EGRID, ENT, EDGE_SMEM>>>(ei, W2, b2, Wg, bg, out, E, N);
    norm_kernel<<<(N * 16 + 255) / 256, 256>>>(out, N);
}